// round 9
// baseline (speedup 1.0000x reference)
#include <cuda_runtime.h>
#include <cuda_bf16.h>
#include <cstdint>
#include <math.h>

#define B_  4
#define S_  1024
#define D_  1024
#define H_  16
#define DK_ 64

// ---------------- scratch (static device globals; no allocation) ------------
// activations hi/lo for q,k,v stacked: [3][B*S*D]
__device__ __align__(128) __nv_bfloat16 g_Ahi[3*B_*S_*D_];
__device__ __align__(128) __nv_bfloat16 g_Alo[3*B_*S_*D_];
// weights hi/lo for Wq,Wk,Wv,Wo stacked: [4][D*D]
__device__ __align__(128) __nv_bfloat16 g_Whi[4*D_*D_];
__device__ __align__(128) __nv_bfloat16 g_Wlo[4*D_*D_];
// projected Q/K/V head-split [B,H,S,DK], hi/lo
__device__ __align__(128) __nv_bfloat16 g_Qhi[B_*H_*S_*DK_];
__device__ __align__(128) __nv_bfloat16 g_Qlo[B_*H_*S_*DK_];
__device__ __align__(128) __nv_bfloat16 g_Khi[B_*H_*S_*DK_];
__device__ __align__(128) __nv_bfloat16 g_Klo[B_*H_*S_*DK_];
__device__ __align__(128) __nv_bfloat16 g_Vhi[B_*H_*S_*DK_];
__device__ __align__(128) __nv_bfloat16 g_Vlo[B_*H_*S_*DK_];
// attention output (ctx) [B,S,D], hi/lo
__device__ __align__(128) __nv_bfloat16 g_Chi[B_*S_*D_];
__device__ __align__(128) __nv_bfloat16 g_Clo[B_*S_*D_];

// ============================================================================
// helpers (family-portable PTX only: ldmatrix / mma.sync / cp.async)
// ============================================================================
static __device__ __forceinline__ uint32_t smem_u32(const void* p) {
    uint32_t a;
    asm("{ .reg .u64 t; cvta.to.shared.u64 t, %1; cvt.u32.u64 %0, t; }"
        : "=r"(a) : "l"(p));
    return a;
}

#define CP_ASYNC16(dst_u32, src_ptr) \
    asm volatile("cp.async.cg.shared.global [%0], [%1], 16;" \
                 :: "r"(dst_u32), "l"(src_ptr))
#define CP_COMMIT()  asm volatile("cp.async.commit_group;")
#define CP_WAIT1()   asm volatile("cp.async.wait_group 1;")

#define LDSM_X4(r0,r1,r2,r3, addr) \
    asm volatile("ldmatrix.sync.aligned.m8n8.x4.shared.b16 {%0,%1,%2,%3}, [%4];" \
                 : "=r"(r0),"=r"(r1),"=r"(r2),"=r"(r3) : "r"(addr))
#define LDSM_X4_T(r0,r1,r2,r3, addr) \
    asm volatile("ldmatrix.sync.aligned.m8n8.x4.trans.shared.b16 {%0,%1,%2,%3}, [%4];" \
                 : "=r"(r0),"=r"(r1),"=r"(r2),"=r"(r3) : "r"(addr))

#define MMA_BF16(c, a, b) \
    asm volatile("mma.sync.aligned.m16n8k16.row.col.f32.bf16.bf16.f32 " \
                 "{%0,%1,%2,%3}, {%4,%5,%6,%7}, {%8,%9}, {%0,%1,%2,%3};" \
                 : "+f"((c)[0]), "+f"((c)[1]), "+f"((c)[2]), "+f"((c)[3]) \
                 : "r"((a)[0]), "r"((a)[1]), "r"((a)[2]), "r"((a)[3]), \
                   "r"((b)[0]), "r"((b)[1]))
// B operands given as two separate regs (for x4-loaded B fragment pairs)
#define MMA_BF16_B2(c, a, b0, b1) \
    asm volatile("mma.sync.aligned.m16n8k16.row.col.f32.bf16.bf16.f32 " \
                 "{%0,%1,%2,%3}, {%4,%5,%6,%7}, {%8,%9}, {%0,%1,%2,%3};" \
                 : "+f"((c)[0]), "+f"((c)[1]), "+f"((c)[2]), "+f"((c)[3]) \
                 : "r"((a)[0]), "r"((a)[1]), "r"((a)[2]), "r"((a)[3]), \
                   "r"(b0), "r"(b1))

static __device__ __forceinline__ uint32_t bf2pack(float a, float b) {
    __nv_bfloat162 t = __floats2bfloat162_rn(a, b);
    return *reinterpret_cast<uint32_t*>(&t);
}
static __device__ __forceinline__ uint32_t split_pack(float a, float b, uint32_t& lo) {
    __nv_bfloat16 ha = __float2bfloat16(a), hb = __float2bfloat16(b);
    lo = bf2pack(a - __bfloat162float(ha), b - __bfloat162float(hb));
    __nv_bfloat162 t = __halves2bfloat162(ha, hb);
    return *reinterpret_cast<uint32_t*>(&t);
}

// ============================================================================
// split kernels (batched; one launch each)
// ============================================================================
static __device__ __forceinline__ void split4(const float* __restrict__ x,
                                              __nv_bfloat16* __restrict__ hi,
                                              __nv_bfloat16* __restrict__ lo, int i)
{
    float4 v = ((const float4*)x)[i];
    __nv_bfloat16 h0 = __float2bfloat16(v.x);
    __nv_bfloat16 h1 = __float2bfloat16(v.y);
    __nv_bfloat16 h2 = __float2bfloat16(v.z);
    __nv_bfloat16 h3 = __float2bfloat16(v.w);
    __nv_bfloat16 l0 = __float2bfloat16(v.x - __bfloat162float(h0));
    __nv_bfloat16 l1 = __float2bfloat16(v.y - __bfloat162float(h1));
    __nv_bfloat16 l2 = __float2bfloat16(v.z - __bfloat162float(h2));
    __nv_bfloat16 l3 = __float2bfloat16(v.w - __bfloat162float(h3));
    ((__nv_bfloat162*)hi)[2*i+0] = __halves2bfloat162(h0, h1);
    ((__nv_bfloat162*)hi)[2*i+1] = __halves2bfloat162(h2, h3);
    ((__nv_bfloat162*)lo)[2*i+0] = __halves2bfloat162(l0, l1);
    ((__nv_bfloat162*)lo)[2*i+1] = __halves2bfloat162(l2, l3);
}

// 4 weights in one launch: grid (nW4/256, 4)
__global__ void split_w4(const float* __restrict__ w0, const float* __restrict__ w1,
                         const float* __restrict__ w2, const float* __restrict__ w3,
                         __nv_bfloat16* __restrict__ hi, __nv_bfloat16* __restrict__ lo)
{
    const int z = blockIdx.y;
    const int i = blockIdx.x * blockDim.x + threadIdx.x;
    const float* w = (z == 0) ? w0 : (z == 1) ? w1 : (z == 2) ? w2 : w3;
    const int off4 = z * (D_ * D_ / 4);
    split4(w, hi + (size_t)off4 * 4, lo + (size_t)off4 * 4, i);
}

// 3 activations in one launch: grid (nA4/256, 3)
__global__ void split_a3(const float* __restrict__ a0, const float* __restrict__ a1,
                         const float* __restrict__ a2,
                         __nv_bfloat16* __restrict__ hi, __nv_bfloat16* __restrict__ lo)
{
    const int z = blockIdx.y;
    const int i = blockIdx.x * blockDim.x + threadIdx.x;
    const float* a = (z == 0) ? a0 : (z == 1) ? a1 : a2;
    const int off4 = z * (B_ * S_ * D_ / 4);
    split4(a, hi + (size_t)off4 * 4, lo + (size_t)off4 * 4, i);
}

// ============================================================================
// shared HMMA GEMM body: C[4096,1024] = A @ W^T + bias, split-bf16 3-product.
// CTA tile 128x128, BK=32, 3-stage cp.async, 256 thr, warp 64x32.
// ONE syncthreads per k-iter (3-stage ring makes the bottom barrier redundant).
// B fragments via ldmatrix.x4 over 16 n-rows.
// MODE 0: f32 row-major out. MODE 1: bf16 hi/lo head-split out.
// ============================================================================
#define GH_ROWB   80
#define GH_ARR    (128 * GH_ROWB)
#define GH_STAGE  (4 * GH_ARR)
#define GH_SMEM   (3 * GH_STAGE)
#define GH_NK     (D_ / 32)

template<int MODE>
static __device__ __forceinline__
void gemm_body(char* smem,
               const __nv_bfloat16* __restrict__ Ahi, const __nv_bfloat16* __restrict__ Alo,
               const __nv_bfloat16* __restrict__ Bhi, const __nv_bfloat16* __restrict__ Blo,
               const float* __restrict__ bias, float* __restrict__ C,
               __nv_bfloat16* __restrict__ Chi, __nv_bfloat16* __restrict__ Clo,
               int bm, int bn)
{
    const uint32_t sb = smem_u32(smem);
    const int tid  = threadIdx.x;
    const int wid  = tid >> 5;
    const int lane = tid & 31;
    const int wm = (wid >> 2) * 64;
    const int wn = (wid & 3) * 32;

    const int c0r = tid >> 2,         c0c = tid & 3;
    const int c1r = (tid + 256) >> 2, c1c = (tid + 256) & 3;

    auto load_stage = [&](int kt, int slot) {
        const int k0 = kt * 32;
        const uint32_t s0 = sb + slot * GH_STAGE;
        const __nv_bfloat16* g;
        uint32_t d;
        g = Ahi + (size_t)(bm + c0r) * D_ + k0 + c0c * 8;
        d = s0 + c0r * GH_ROWB + c0c * 16;               CP_ASYNC16(d, g);
        g = Ahi + (size_t)(bm + c1r) * D_ + k0 + c1c * 8;
        d = s0 + c1r * GH_ROWB + c1c * 16;               CP_ASYNC16(d, g);
        g = Alo + (size_t)(bm + c0r) * D_ + k0 + c0c * 8;
        d = s0 + GH_ARR + c0r * GH_ROWB + c0c * 16;      CP_ASYNC16(d, g);
        g = Alo + (size_t)(bm + c1r) * D_ + k0 + c1c * 8;
        d = s0 + GH_ARR + c1r * GH_ROWB + c1c * 16;      CP_ASYNC16(d, g);
        g = Bhi + (size_t)(bn + c0r) * D_ + k0 + c0c * 8;
        d = s0 + 2 * GH_ARR + c0r * GH_ROWB + c0c * 16;  CP_ASYNC16(d, g);
        g = Bhi + (size_t)(bn + c1r) * D_ + k0 + c1c * 8;
        d = s0 + 2 * GH_ARR + c1r * GH_ROWB + c1c * 16;  CP_ASYNC16(d, g);
        g = Blo + (size_t)(bn + c0r) * D_ + k0 + c0c * 8;
        d = s0 + 3 * GH_ARR + c0r * GH_ROWB + c0c * 16;  CP_ASYNC16(d, g);
        g = Blo + (size_t)(bn + c1r) * D_ + k0 + c1c * 8;
        d = s0 + 3 * GH_ARR + c1r * GH_ROWB + c1c * 16;  CP_ASYNC16(d, g);
    };

    float acc[4][4][4];
#pragma unroll
    for (int i = 0; i < 4; i++)
#pragma unroll
        for (int j = 0; j < 4; j++)
#pragma unroll
            for (int r = 0; r < 4; r++) acc[i][j][r] = 0.f;

    load_stage(0, 0); CP_COMMIT();
    load_stage(1, 1); CP_COMMIT();

    const int aRow = lane & 15;
    const int aChk = (lane >> 4) * 16;
    // B x4: lanes 0-15 -> 16 n-rows at k-chunk 0, lanes 16-31 -> same rows chunk 16B
    const int bRow16 = lane & 15;
    const int bChk   = (lane >> 4) * 16;

#pragma unroll 1
    for (int kt = 0; kt < GH_NK; kt++) {
        CP_WAIT1();
        __syncthreads();           // single barrier per iteration (3-stage ring)
        if (kt + 2 < GH_NK) { load_stage(kt + 2, (kt + 2) % 3); }
        CP_COMMIT();

        const uint32_t s0 = sb + (kt % 3) * GH_STAGE;
#pragma unroll
        for (int ks = 0; ks < 2; ks++) {
            const int kb = ks * 32;
            uint32_t ah[4][4], al[4][4], bh[2][4], bl[2][4];
#pragma unroll
            for (int mt = 0; mt < 4; mt++) {
                uint32_t ro = (wm + mt * 16 + aRow) * GH_ROWB + kb + aChk;
                LDSM_X4(ah[mt][0], ah[mt][1], ah[mt][2], ah[mt][3], s0 + ro);
                LDSM_X4(al[mt][0], al[mt][1], al[mt][2], al[mt][3], s0 + GH_ARR + ro);
            }
#pragma unroll
            for (int np = 0; np < 2; np++) {
                uint32_t ro = (wn + np * 16 + bRow16) * GH_ROWB + kb + bChk;
                LDSM_X4(bh[np][0], bh[np][1], bh[np][2], bh[np][3], s0 + 2 * GH_ARR + ro);
                LDSM_X4(bl[np][0], bl[np][1], bl[np][2], bl[np][3], s0 + 3 * GH_ARR + ro);
            }
#pragma unroll
            for (int mt = 0; mt < 4; mt++)
#pragma unroll
                for (int np = 0; np < 2; np++) {
                    MMA_BF16_B2(acc[mt][2*np],   ah[mt], bh[np][0], bh[np][2]);
                    MMA_BF16_B2(acc[mt][2*np],   ah[mt], bl[np][0], bl[np][2]);
                    MMA_BF16_B2(acc[mt][2*np],   al[mt], bh[np][0], bh[np][2]);
                    MMA_BF16_B2(acc[mt][2*np+1], ah[mt], bh[np][1], bh[np][3]);
                    MMA_BF16_B2(acc[mt][2*np+1], ah[mt], bl[np][1], bl[np][3]);
                    MMA_BF16_B2(acc[mt][2*np+1], al[mt], bh[np][1], bh[np][3]);
                }
        }
    }

    // ---- epilogue ----
    const int gid = lane >> 2;
    const int tig = lane & 3;
#pragma unroll
    for (int mt = 0; mt < 4; mt++) {
#pragma unroll
        for (int nt = 0; nt < 4; nt++) {
            int row = bm + wm + mt * 16 + gid;
            int col = bn + wn + nt * 8 + tig * 2;
            float2 bv = *(const float2*)(bias + col);
            float v00 = acc[mt][nt][0] + bv.x, v01 = acc[mt][nt][1] + bv.y;
            float v10 = acc[mt][nt][2] + bv.x, v11 = acc[mt][nt][3] + bv.y;
            if (MODE == 0) {
                *(float2*)(C + (size_t)row * D_ + col)       = make_float2(v00, v01);
                *(float2*)(C + (size_t)(row + 8) * D_ + col) = make_float2(v10, v11);
            } else {
                int h = col >> 6, dk = col & 63;
                int b0 = row >> 10, ss0 = row & 1023;
                int r8 = row + 8;
                int b1 = r8 >> 10, ss1 = r8 & 1023;
                size_t i0 = ((size_t)(b0 * H_ + h) * S_ + ss0) * DK_ + dk;
                size_t i1 = ((size_t)(b1 * H_ + h) * S_ + ss1) * DK_ + dk;
                uint32_t lo0, lo1;
                uint32_t hi0 = split_pack(v00, v01, lo0);
                uint32_t hi1 = split_pack(v10, v11, lo1);
                *(uint32_t*)(Chi + i0) = hi0;  *(uint32_t*)(Clo + i0) = lo0;
                *(uint32_t*)(Chi + i1) = hi1;  *(uint32_t*)(Clo + i1) = lo1;
            }
        }
    }
}

// fused Q/K/V projection: grid (8, 32, 3); z selects activation/weight/bias/dst
__global__ __launch_bounds__(256, 1)
void gemm_qkv(const __nv_bfloat16* __restrict__ AhiB, const __nv_bfloat16* __restrict__ AloB,
              const __nv_bfloat16* __restrict__ WhiB, const __nv_bfloat16* __restrict__ WloB,
              const float* __restrict__ bq, const float* __restrict__ bk,
              const float* __restrict__ bv,
              __nv_bfloat16* __restrict__ Qhi, __nv_bfloat16* __restrict__ Qlo,
              __nv_bfloat16* __restrict__ Khi, __nv_bfloat16* __restrict__ Klo,
              __nv_bfloat16* __restrict__ Vhi, __nv_bfloat16* __restrict__ Vlo)
{
    extern __shared__ char smem[];
    const int z = blockIdx.z;
    const size_t ao = (size_t)z * (B_ * S_ * D_);
    const size_t wo = (size_t)z * (D_ * D_);
    const float* bias = (z == 0) ? bq : (z == 1) ? bk : bv;
    __nv_bfloat16* Chi = (z == 0) ? Qhi : (z == 1) ? Khi : Vhi;
    __nv_bfloat16* Clo = (z == 0) ? Qlo : (z == 1) ? Klo : Vlo;
    gemm_body<1>(smem, AhiB + ao, AloB + ao, WhiB + wo, WloB + wo,
                 bias, nullptr, Chi, Clo, blockIdx.y * 128, blockIdx.x * 128);
}

// output projection: f32 out
__global__ __launch_bounds__(256, 1)
void gemm_out(const __nv_bfloat16* __restrict__ Ahi, const __nv_bfloat16* __restrict__ Alo,
              const __nv_bfloat16* __restrict__ Whi, const __nv_bfloat16* __restrict__ Wlo,
              const float* __restrict__ bias, float* __restrict__ C)
{
    extern __shared__ char smem[];
    gemm_body<0>(smem, Ahi, Alo, Whi, Wlo, bias, C, nullptr, nullptr,
                 blockIdx.y * 128, blockIdx.x * 128);
}

// ============================================================================
// Flash attention, HMMA split-bf16, causal. 128 q-rows/CTA, 3-stage KV ring,
// single barrier per k-block iteration.
// smem: Qhi/Qlo (2 x 18432) + 3 stages x {Khi,Klo,Vhi,Vlo} (3 x 36864) = 147456
// ============================================================================
#define AT_ROWB  144
#define AT_QARR  (128 * AT_ROWB)
#define AT_KARR  (64 * AT_ROWB)
#define AT_KV0   (2 * AT_QARR)
#define AT_STG   (4 * AT_KARR)
#define AT_SMEM  (AT_KV0 + 3 * AT_STG)   // 147456

__global__ __launch_bounds__(256, 1)
void flash_attn_tc(const __nv_bfloat16* __restrict__ Qhi, const __nv_bfloat16* __restrict__ Qlo,
                   const __nv_bfloat16* __restrict__ Khi, const __nv_bfloat16* __restrict__ Klo,
                   const __nv_bfloat16* __restrict__ Vhi, const __nv_bfloat16* __restrict__ Vlo,
                   __nv_bfloat16* __restrict__ Chi, __nv_bfloat16* __restrict__ Clo)
{
    extern __shared__ char smem[];
    const uint32_t sb = smem_u32(smem);
    const int tid  = threadIdx.x;
    const int wid  = tid >> 5;
    const int lane = tid & 31;
    const int iq   = 7 - blockIdx.x;       // heavy CTAs first
    const int bh   = blockIdx.y;
    const int qg0  = iq * 128;
    const int nkb  = 2 * iq + 2;

    auto load_kv = [&](int kb, int slot) {
        const uint32_t s0 = sb + AT_KV0 + slot * AT_STG;
        const int rowbase = bh * S_ + kb * 64;
        const int i0 = tid, i1 = tid + 256;
        const int r0 = i0 >> 3, c0 = i0 & 7, r1 = i1 >> 3, c1 = i1 & 7;
        const size_t g0 = (size_t)(rowbase + r0) * DK_ + c0 * 8;
        const size_t g1 = (size_t)(rowbase + r1) * DK_ + c1 * 8;
        const uint32_t d0 = r0 * AT_ROWB + c0 * 16;
        const uint32_t d1 = r1 * AT_ROWB + c1 * 16;
        CP_ASYNC16(s0 + d0,               Khi + g0);
        CP_ASYNC16(s0 + d1,               Khi + g1);
        CP_ASYNC16(s0 + AT_KARR + d0,     Klo + g0);
        CP_ASYNC16(s0 + AT_KARR + d1,     Klo + g1);
        CP_ASYNC16(s0 + 2*AT_KARR + d0,   Vhi + g0);
        CP_ASYNC16(s0 + 2*AT_KARR + d1,   Vhi + g1);
        CP_ASYNC16(s0 + 3*AT_KARR + d0,   Vlo + g0);
        CP_ASYNC16(s0 + 3*AT_KARR + d1,   Vlo + g1);
    };

    // ---- prologue: group0 = Q(hi+lo) + KV block 0, group1 = KV block 1 ----
#pragma unroll
    for (int t = 0; t < 8; t++) {
        int f = tid + t * 256;
        int arr = f >> 10;
        int idx = f & 1023;
        int row = idx >> 3, c = idx & 7;
        const __nv_bfloat16* src =
            (arr ? Qlo : Qhi) + (size_t)(bh * S_ + qg0 + row) * DK_ + c * 8;
        CP_ASYNC16(sb + arr * AT_QARR + row * AT_ROWB + c * 16, src);
    }
    load_kv(0, 0);
    CP_COMMIT();
    load_kv(1, 1);
    CP_COMMIT();

    CP_WAIT1();        // group0 (Q + KV0) complete
    __syncthreads();

    // ---- preload Q fragments ----
    uint32_t qh[4][4], ql[4][4];
    {
        uint32_t rowb = (uint32_t)((wid * 16 + (lane & 15)) * AT_ROWB + (lane >> 4) * 16);
#pragma unroll
        for (int kc = 0; kc < 4; kc++) {
            LDSM_X4(qh[kc][0], qh[kc][1], qh[kc][2], qh[kc][3], sb + rowb + kc * 32);
            LDSM_X4(ql[kc][0], ql[kc][1], ql[kc][2], ql[kc][3], sb + AT_QARR + rowb + kc * 32);
        }
    }

    float m0 = -1e30f, m1 = -1e30f, l0 = 0.f, l1 = 0.f;
    float of[8][4];
#pragma unroll
    for (int dt = 0; dt < 8; dt++)
#pragma unroll
        for (int e = 0; e < 4; e++) of[dt][e] = 0.f;

    const int rq = qg0 + wid * 16 + (lane >> 2);

    for (int kb = 0; kb < nkb; kb++) {
        CP_WAIT1();                 // KV block kb complete
        __syncthreads();            // single barrier (3-stage ring)
        if (kb + 2 < nkb) { load_kv(kb + 2, (kb + 2) % 3); CP_COMMIT(); }

        const bool active = (kb * 64 <= qg0 + wid * 16 + 15);
        if (active) {
            const uint32_t kbase = sb + AT_KV0 + (kb % 3) * AT_STG;

            // ---- S = Q K^T (3-product) ----
            float sf[8][4];
#pragma unroll
            for (int nt = 0; nt < 8; nt++)
#pragma unroll
                for (int e = 0; e < 4; e++) sf[nt][e] = 0.f;

            const uint32_t kRow = (uint32_t)((lane & 7) + ((lane >> 4) << 3));
            const uint32_t kChk = (uint32_t)(((lane >> 3) & 1) << 4);
#pragma unroll
            for (int kc = 0; kc < 4; kc++) {
#pragma unroll
                for (int ntp = 0; ntp < 4; ntp++) {
                    uint32_t addr = kbase + (ntp * 16 + kRow) * AT_ROWB + kc * 32 + kChk;
                    uint32_t kh2[4], kl2[4];
                    LDSM_X4(kh2[0], kh2[1], kh2[2], kh2[3], addr);
                    LDSM_X4(kl2[0], kl2[1], kl2[2], kl2[3], addr + AT_KARR);
                    MMA_BF16(sf[2*ntp],   qh[kc], &kh2[0]);
                    MMA_BF16(sf[2*ntp],   qh[kc], &kl2[0]);
                    MMA_BF16(sf[2*ntp],   ql[kc], &kh2[0]);
                    MMA_BF16(sf[2*ntp+1], qh[kc], &kh2[2]);
                    MMA_BF16(sf[2*ntp+1], qh[kc], &kl2[2]);
                    MMA_BF16(sf[2*ntp+1], ql[kc], &kh2[2]);
                }
            }

            // ---- scale + causal mask ----
            const int colb = kb * 64 + (lane & 3) * 2;
            const bool dm = (kb * 64 + 63 > qg0 + wid * 16);
#pragma unroll
            for (int nt = 0; nt < 8; nt++) {
                int c0 = colb + nt * 8, c1 = c0 + 1;
                if (dm) {
                    sf[nt][0] = (c0 > rq)     ? -1e30f : sf[nt][0] * 0.125f;
                    sf[nt][1] = (c1 > rq)     ? -1e30f : sf[nt][1] * 0.125f;
                    sf[nt][2] = (c0 > rq + 8) ? -1e30f : sf[nt][2] * 0.125f;
                    sf[nt][3] = (c1 > rq + 8) ? -1e30f : sf[nt][3] * 0.125f;
                } else {
                    sf[nt][0] *= 0.125f; sf[nt][1] *= 0.125f;
                    sf[nt][2] *= 0.125f; sf[nt][3] *= 0.125f;
                }
            }

            // ---- online softmax ----
            float mx0 = sf[0][0], mx1 = sf[0][2];
#pragma unroll
            for (int nt = 0; nt < 8; nt++) {
                mx0 = fmaxf(mx0, fmaxf(sf[nt][0], sf[nt][1]));
                mx1 = fmaxf(mx1, fmaxf(sf[nt][2], sf[nt][3]));
            }
            mx0 = fmaxf(mx0, __shfl_xor_sync(0xffffffffu, mx0, 1));
            mx0 = fmaxf(mx0, __shfl_xor_sync(0xffffffffu, mx0, 2));
            mx1 = fmaxf(mx1, __shfl_xor_sync(0xffffffffu, mx1, 1));
            mx1 = fmaxf(mx1, __shfl_xor_sync(0xffffffffu, mx1, 2));
            float mn0 = fmaxf(m0, mx0), mn1 = fmaxf(m1, mx1);
            float cr0 = __expf(m0 - mn0), cr1 = __expf(m1 - mn1);
            m0 = mn0; m1 = mn1;
            float rs0 = 0.f, rs1 = 0.f;
#pragma unroll
            for (int nt = 0; nt < 8; nt++) {
                sf[nt][0] = __expf(sf[nt][0] - mn0); rs0 += sf[nt][0];
                sf[nt][1] = __expf(sf[nt][1] - mn0); rs0 += sf[nt][1];
                sf[nt][2] = __expf(sf[nt][2] - mn1); rs1 += sf[nt][2];
                sf[nt][3] = __expf(sf[nt][3] - mn1); rs1 += sf[nt][3];
            }
            rs0 += __shfl_xor_sync(0xffffffffu, rs0, 1);
            rs0 += __shfl_xor_sync(0xffffffffu, rs0, 2);
            rs1 += __shfl_xor_sync(0xffffffffu, rs1, 1);
            rs1 += __shfl_xor_sync(0xffffffffu, rs1, 2);
            l0 = l0 * cr0 + rs0;
            l1 = l1 * cr1 + rs1;
#pragma unroll
            for (int dt = 0; dt < 8; dt++) {
                of[dt][0] *= cr0; of[dt][1] *= cr0;
                of[dt][2] *= cr1; of[dt][3] *= cr1;
            }

            // ---- O += P V (P split in-register, V hi/lo, trans ldmatrix) ----
            const uint32_t vRowB = (uint32_t)(lane & 15) * AT_ROWB;
            const uint32_t vChk  = (uint32_t)(lane >> 4) * 16;
#pragma unroll
            for (int kc = 0; kc < 4; kc++) {
                uint32_t phi[4], plo[4];
                phi[0] = split_pack(sf[2*kc][0],   sf[2*kc][1],   plo[0]);
                phi[1] = split_pack(sf[2*kc][2],   sf[2*kc][3],   plo[1]);
                phi[2] = split_pack(sf[2*kc+1][0], sf[2*kc+1][1], plo[2]);
                phi[3] = split_pack(sf[2*kc+1][2], sf[2*kc+1][3], plo[3]);
#pragma unroll
                for (int dtp = 0; dtp < 4; dtp++) {
                    uint32_t addr = kbase + 2 * AT_KARR
                                  + (uint32_t)(kc * 16) * AT_ROWB + vRowB
                                  + (uint32_t)(dtp * 2) * 16 + vChk;
                    uint32_t vh2[4], vl2[4];
                    LDSM_X4_T(vh2[0], vh2[1], vh2[2], vh2[3], addr);
                    LDSM_X4_T(vl2[0], vl2[1], vl2[2], vl2[3], addr + AT_KARR);
                    MMA_BF16(of[2*dtp],   phi, &vh2[0]);
                    MMA_BF16(of[2*dtp],   phi, &vl2[0]);
                    MMA_BF16(of[2*dtp],   plo, &vh2[0]);
                    MMA_BF16(of[2*dtp+1], phi, &vh2[2]);
                    MMA_BF16(of[2*dtp+1], phi, &vl2[2]);
                    MMA_BF16(of[2*dtp+1], plo, &vh2[2]);
                }
            }
        }
    }

    // ---- epilogue: normalize, split hi/lo, write ctx [B,S,D] ----
    const int b = bh >> 4, h = bh & 15;
    const float inv0 = 1.f / l0, inv1 = 1.f / l1;
#pragma unroll
    for (int dt = 0; dt < 8; dt++) {
        int col = h * 64 + dt * 8 + (lane & 3) * 2;
        size_t o0 = (size_t)(b * S_ + rq) * D_ + col;
        size_t o1 = (size_t)(b * S_ + rq + 8) * D_ + col;
        uint32_t lo0, lo1;
        uint32_t hi0 = split_pack(of[dt][0] * inv0, of[dt][1] * inv0, lo0);
        uint32_t hi1 = split_pack(of[dt][2] * inv1, of[dt][3] * inv1, lo1);
        *(uint32_t*)(Chi + o0) = hi0;  *(uint32_t*)(Clo + o0) = lo0;
        *(uint32_t*)(Chi + o1) = hi1;  *(uint32_t*)(Clo + o1) = lo1;
    }
}

// ============================================================================
// launch  (5 launches total)
// ============================================================================
extern "C" void kernel_launch(void* const* d_in, const int* in_sizes, int n_in,
                              void* d_out, int out_size)
{
    const float* q  = (const float*)d_in[0];
    const float* k  = (const float*)d_in[1];
    const float* v  = (const float*)d_in[2];
    // d_in[3] = mask (exact causal tril; handled analytically in-kernel)
    const float* Wq = (const float*)d_in[4];
    const float* bq = (const float*)d_in[5];
    const float* Wk = (const float*)d_in[6];
    const float* bk = (const float*)d_in[7];
    const float* Wv = (const float*)d_in[8];
    const float* bv = (const float*)d_in[9];
    const float* Wo = (const float*)d_in[10];
    const float* bo = (const float*)d_in[11];
    float* out = (float*)d_out;

    __nv_bfloat16 *Ahi, *Alo, *Whi, *Wlo;
    __nv_bfloat16 *Qhi, *Qlo, *Khi, *Klo, *Vhi, *Vlo, *Chi, *Clo;
    cudaGetSymbolAddress((void**)&Ahi, g_Ahi);
    cudaGetSymbolAddress((void**)&Alo, g_Alo);
    cudaGetSymbolAddress((void**)&Whi, g_Whi);
    cudaGetSymbolAddress((void**)&Wlo, g_Wlo);
    cudaGetSymbolAddress((void**)&Qhi, g_Qhi);
    cudaGetSymbolAddress((void**)&Qlo, g_Qlo);
    cudaGetSymbolAddress((void**)&Khi, g_Khi);
    cudaGetSymbolAddress((void**)&Klo, g_Klo);
    cudaGetSymbolAddress((void**)&Vhi, g_Vhi);
    cudaGetSymbolAddress((void**)&Vlo, g_Vlo);
    cudaGetSymbolAddress((void**)&Chi, g_Chi);
    cudaGetSymbolAddress((void**)&Clo, g_Clo);

    cudaFuncSetAttribute(gemm_qkv, cudaFuncAttributeMaxDynamicSharedMemorySize, GH_SMEM);
    cudaFuncSetAttribute(gemm_out, cudaFuncAttributeMaxDynamicSharedMemorySize, GH_SMEM);
    cudaFuncSetAttribute(flash_attn_tc, cudaFuncAttributeMaxDynamicSharedMemorySize, AT_SMEM);

    const int nA4 = (B_ * S_ * D_) / 4;
    const int nW4 = (D_ * D_) / 4;

    // 1) all weight splits (Wq,Wk,Wv,Wo)
    split_w4<<<dim3(nW4 / 256, 4), 256>>>(Wq, Wk, Wv, Wo, Whi, Wlo);
    // 2) all activation splits (q,k,v)
    split_a3<<<dim3(nA4 / 256, 3), 256>>>(q, k, v, Ahi, Alo);
    // 3) fused Q/K/V projection (768 CTAs, one launch)
    gemm_qkv<<<dim3(D_ / 128, (B_ * S_) / 128, 3), 256, GH_SMEM>>>(
        Ahi, Alo, Whi, Wlo, bq, bk, bv, Qhi, Qlo, Khi, Klo, Vhi, Vlo);
    // 4) attention (writes ctx hi/lo directly)
    flash_attn_tc<<<dim3(8, B_ * H_), 256, AT_SMEM>>>(Qhi, Qlo, Khi, Klo, Vhi, Vlo, Chi, Clo);
    // 5) output projection (Wo = weight index 3)
    gemm_out<<<dim3(D_ / 128, (B_ * S_) / 128), 256, GH_SMEM>>>(
        Chi, Clo, Whi + (size_t)3 * D_ * D_, Wlo + (size_t)3 * D_ * D_, bo, out);
}